// round 15
// baseline (speedup 1.0000x reference)
#include <cuda_runtime.h>
#include <cuda_fp16.h>
#include <cstddef>
#include <cstdint>

#define BSZ 64
#define LSZ 1024
#define DSZ 256
#define NTOK (BSZ * LSZ)   // 65536 tokens

// ---------------- scratch (static __device__ — no allocations) ----------------
__device__ __half  g_xh[(size_t)NTOK * DSZ];        // 32 MB : inputs as fp16
__device__ float   g_xg[(size_t)NTOK * 3 * DSZ];    // 192 MB: [xx | xr' | xu'] per token (fp32)
__device__ __half  g_hf[(size_t)NTOK * DSZ];        // 32 MB : forward hidden states (fp16)
__device__ __half  g_hb[(size_t)NTOK * DSZ];        // 32 MB : backward hidden states (fp16)
__device__ __half  g_wo_h[DSZ * DSZ];               // Wo fp16
__device__ __half  g_wg_h[DSZ * 3 * DSZ];           // composite Wi@[Wx|Ux|Rx] fp16 (256 x 768)
__device__ float   g_bg[3 * DSZ];                   // composite biases
// recurrent weights: [q][k=256][n=128], col n: j=n>>1, n&1 ? Wu : Wr  (interleaved)
__device__ __half  g_wrec[4 * 256 * 128];

// ---------------- prep: pack recurrent weights + Wo ---------------------------
__global__ void prep_kernel(const float* __restrict__ Wr, const float* __restrict__ Wu,
                            const float* __restrict__ Wo) {
    int i = blockIdx.x * blockDim.x + threadIdx.x;
    if (i < DSZ * DSZ) g_wo_h[i] = __float2half_rn(Wo[i]);
    if (i < 4 * 256 * 128) {
        int q = i >> 15;
        int k = (i >> 7) & 255;
        int n = i & 127;
        int col = q * 64 + (n >> 1);
        float v = (n & 1) ? Wu[k * DSZ + col] : Wr[k * DSZ + col];
        g_wrec[i] = __float2half_rn(v);
    }
}

// ---- convert inputs fp32 -> fp16 (once) --------------------------------------
__global__ __launch_bounds__(256) void conv_inp(const float* __restrict__ in) {
    size_t i = (size_t)blockIdx.x * blockDim.x + threadIdx.x;
    if (i >= (size_t)NTOK * DSZ / 8) return;
    float4 a = ((const float4*)in)[2 * i];
    float4 b = ((const float4*)in)[2 * i + 1];
    __half2 h[4] = { __floats2half2_rn(a.x, a.y), __floats2half2_rn(a.z, a.w),
                     __floats2half2_rn(b.x, b.y), __floats2half2_rn(b.z, b.w) };
    ((uint4*)g_xh)[i] = *(uint4*)h;
}

// ---- composite weight: W'[256][768] = Wi[256,256] @ [Wx|Ux|Rx], fp32 -> fp16
__global__ __launch_bounds__(256) void comp_w_kernel(
        const float* __restrict__ Wi, const float* __restrict__ Wx,
        const float* __restrict__ Ux, const float* __restrict__ Rx) {
    __shared__ float As[16][65];   // As[d][row]
    __shared__ float Bs[16][64];
    const int bn = blockIdx.x;     // 0..11
    const int bm = blockIdx.y;     // 0..3
    const float* src = (bn < 4) ? Wx : (bn < 8) ? Ux : Rx;
    const int nc0 = (bn & 3) * 64;
    const int tid = threadIdx.x;
    const int tx = tid & 15, ty = tid >> 4;

    float acc[4][4];
#pragma unroll
    for (int i = 0; i < 4; i++)
#pragma unroll
        for (int j = 0; j < 4; j++) acc[i][j] = 0.f;

    for (int d0 = 0; d0 < 256; d0 += 16) {
#pragma unroll
        for (int it = 0; it < 4; it++) {
            int idx = it * 256 + tid;
            int row = idx >> 4, c = idx & 15;
            As[c][row] = Wi[(bm * 64 + row) * 256 + d0 + c];
            int r2 = idx >> 6, c2 = idx & 63;
            Bs[r2][c2] = src[(d0 + r2) * 256 + nc0 + c2];
        }
        __syncthreads();
#pragma unroll
        for (int k = 0; k < 16; k++) {
            float a[4], b[4];
#pragma unroll
            for (int i = 0; i < 4; i++) a[i] = As[k][ty * 4 + i];
#pragma unroll
            for (int j = 0; j < 4; j++) b[j] = Bs[k][tx * 4 + j];
#pragma unroll
            for (int i = 0; i < 4; i++)
#pragma unroll
                for (int j = 0; j < 4; j++) acc[i][j] = fmaf(a[i], b[j], acc[i][j]);
        }
        __syncthreads();
    }
#pragma unroll
    for (int i = 0; i < 4; i++)
#pragma unroll
        for (int j = 0; j < 4; j++)
            g_wg_h[(size_t)(bm * 64 + ty * 4 + i) * 768 + bn * 64 + tx * 4 + j] =
                __float2half_rn(acc[i][j]);
}

// ---- composite bias: warp-parallel (768 blocks x 32 lanes) -------------------
__global__ void comp_b_kernel(const float* __restrict__ bi,
                              const float* __restrict__ Wx, const float* __restrict__ Wxb,
                              const float* __restrict__ Ux, const float* __restrict__ Uxb,
                              const float* __restrict__ Rx, const float* __restrict__ Rxb,
                              const float* __restrict__ Wrb, const float* __restrict__ Wub) {
    int n = blockIdx.x;
    int lane = threadIdx.x;
    const float* src; int nl; float base;
    if (n < 256)      { src = Wx; nl = n;       base = Wxb[nl]; }
    else if (n < 512) { src = Ux; nl = n - 256; base = Uxb[nl] + Wrb[nl]; }
    else              { src = Rx; nl = n - 512; base = Rxb[nl] + Wub[nl]; }
    float s = 0.f;
    for (int d = lane; d < 256; d += 32) s = fmaf(bi[d], src[d * 256 + nl], s);
#pragma unroll
    for (int off = 16; off; off >>= 1) s += __shfl_xor_sync(0xffffffffu, s, off);
    if (lane == 0) g_bg[n] = s + base;
}

// ---------------- mma / ldmatrix helpers --------------------------------------
__device__ __forceinline__ void ldmatrix_x4(uint32_t* r, const __half* p) {
    uint32_t addr = (uint32_t)__cvta_generic_to_shared(p);
    asm volatile("ldmatrix.sync.aligned.m8n8.x4.shared.b16 {%0,%1,%2,%3}, [%4];"
                 : "=r"(r[0]), "=r"(r[1]), "=r"(r[2]), "=r"(r[3]) : "r"(addr));
}
__device__ __forceinline__ void ldmatrix_x2t(uint32_t* r, const __half* p) {
    uint32_t addr = (uint32_t)__cvta_generic_to_shared(p);
    asm volatile("ldmatrix.sync.aligned.m8n8.x2.trans.shared.b16 {%0,%1}, [%2];"
                 : "=r"(r[0]), "=r"(r[1]) : "r"(addr));
}
__device__ __forceinline__ void mma16816(float* c, const uint32_t* a, const uint32_t* b) {
    asm volatile("mma.sync.aligned.m16n8k16.row.col.f32.f16.f16.f32 "
                 "{%0,%1,%2,%3}, {%4,%5,%6,%7}, {%8,%9}, {%0,%1,%2,%3};"
                 : "+f"(c[0]), "+f"(c[1]), "+f"(c[2]), "+f"(c[3])
                 : "r"(a[0]), "r"(a[1]), "r"(a[2]), "r"(a[3]), "r"(b[0]), "r"(b[1]));
}
__device__ __forceinline__ float tanh_ap(float x) {
    float y; asm("tanh.approx.f32 %0, %1;" : "=f"(y) : "f"(x)); return y;
}

// ---------------- mbarrier / cluster helpers ----------------------------------
__device__ __forceinline__ void bar_init(uint32_t bar, uint32_t cnt) {
    asm volatile("mbarrier.init.shared.b64 [%0], %1;" :: "r"(bar), "r"(cnt) : "memory");
}
__device__ __forceinline__ void bar_expect_tx(uint32_t bar, uint32_t bytes) {
    asm volatile("mbarrier.arrive.expect_tx.shared.b64 _, [%0], %1;"
                 :: "r"(bar), "r"(bytes) : "memory");
}
__device__ __forceinline__ void bar_wait(uint32_t bar, uint32_t phase) {
    asm volatile(
        "{\n\t.reg .pred P;\n\t"
        "WL_%=:\n\t"
        "mbarrier.try_wait.parity.acquire.cta.shared::cta.b64 P, [%0], %1, 0x989680;\n\t"
        "@P bra WD_%=;\n\t"
        "bra WL_%=;\n\t"
        "WD_%=:\n\t}"
        :: "r"(bar), "r"(phase) : "memory");
}
__device__ __forceinline__ uint32_t mapa_u32(uint32_t laddr, uint32_t rank) {
    uint32_t r;
    asm volatile("mapa.shared::cluster.u32 %0, %1, %2;" : "=r"(r) : "r"(laddr), "r"(rank));
    return r;
}
__device__ __forceinline__ void st_async_b32(uint32_t raddr, uint32_t val, uint32_t rbar) {
    asm volatile("st.async.shared::cluster.mbarrier::complete_tx::bytes.b32 [%0], %1, [%2];"
                 :: "r"(raddr), "r"(val), "r"(rbar) : "memory");
}

// ---------------- tensor-core GEMM (R14 — validated, unchanged) ----------------
#define A_LD 264
#define B2_LD 136
#define SMEM_GEMM_BYTES ((128 * A_LD + 128 * B2_LD) * 2)   // 102400

template<int AMODE, int OUTH>
__global__ __launch_bounds__(256, 2) void gemm_tc(
        const void* __restrict__ Aa, const void* __restrict__ Ab,
        const __half* __restrict__ Bg, const float* __restrict__ bias,
        void* __restrict__ Cg, int N) {
    extern __shared__ __half sm[];
    __half* As = sm;                     // [128][A_LD]
    __half* Bs = sm + 128 * A_LD;        // [128][B2_LD]

    const int tid  = threadIdx.x;
    const int bm   = blockIdx.y * 128;
    const int bn   = blockIdx.x * 128;
    const int nq   = N >> 3;

    const int wid  = tid >> 5;
    const int lane = tid & 31;
    const int wm   = (wid & 3) * 32;
    const int wn   = (wid >> 2) * 64;
    const int al_r = lane & 15;
    const int al_c = (lane >> 4) << 3;

#pragma unroll
    for (int it = 0; it < 16; it++) {
        int idx = it * 256 + tid;
        int row = idx >> 5;
        int cu  = idx & 31;
        uint4 v;
        if (AMODE == 1) {
            v = ((const uint4*)Aa)[(size_t)(bm + row) * 32 + cu];
        } else {
            uint4 p = ((const uint4*)Aa)[(size_t)(bm + row) * 32 + cu];
            uint4 q = ((const uint4*)Ab)[(size_t)(bm + row) * 32 + cu];
            __half2* pp = (__half2*)&p; const __half2* qq = (const __half2*)&q;
            pp[0] = __hadd2(pp[0], qq[0]); pp[1] = __hadd2(pp[1], qq[1]);
            pp[2] = __hadd2(pp[2], qq[2]); pp[3] = __hadd2(pp[3], qq[3]);
            v = p;
        }
        *(uint4*)(As + row * A_LD + cu * 8) = v;
    }

    float acc[2][8][4];
#pragma unroll
    for (int mt = 0; mt < 2; mt++)
#pragma unroll
        for (int nt = 0; nt < 8; nt++)
#pragma unroll
            for (int i = 0; i < 4; i++) acc[mt][nt][i] = 0.f;

#pragma unroll
    for (int ks2 = 0; ks2 < 2; ks2++) {
        if (ks2) __syncthreads();

#pragma unroll
        for (int it = 0; it < 8; it++) {
            int idx = it * 256 + tid;
            int row = idx >> 4;
            int cu  = idx & 15;
            uint4 v = ((const uint4*)Bg)[(size_t)(ks2 * 128 + row) * nq + (bn >> 3) + cu];
            *(uint4*)(Bs + row * B2_LD + cu * 8) = v;
        }
        __syncthreads();

#pragma unroll
        for (int ks = 0; ks < 8; ks++) {
            const int k0a = ks2 * 128 + ks * 16;
            const int k0b = ks * 16;
            uint32_t a[2][4], b[8][2];
#pragma unroll
            for (int mt = 0; mt < 2; mt++)
                ldmatrix_x4(a[mt], As + (wm + mt * 16 + al_r) * A_LD + k0a + al_c);
#pragma unroll
            for (int nt = 0; nt < 8; nt++)
                ldmatrix_x2t(b[nt], Bs + (k0b + al_r) * B2_LD + wn + nt * 8);
#pragma unroll
            for (int mt = 0; mt < 2; mt++)
#pragma unroll
                for (int nt = 0; nt < 8; nt++)
                    mma16816(acc[mt][nt], a[mt], b[nt]);
        }
    }

#pragma unroll
    for (int mt = 0; mt < 2; mt++) {
#pragma unroll
        for (int nt = 0; nt < 8; nt++) {
            int row = bm + wm + mt * 16 + (lane >> 2);
            int col = bn + wn + nt * 8 + (lane & 3) * 2;
            float b0 = bias[col], b1 = bias[col + 1];
            if (OUTH) {
                __half* C = (__half*)Cg;
                *(__half2*)(C + (size_t)row * N + col) =
                    __floats2half2_rn(acc[mt][nt][0] + b0, acc[mt][nt][1] + b1);
                *(__half2*)(C + (size_t)(row + 8) * N + col) =
                    __floats2half2_rn(acc[mt][nt][2] + b0, acc[mt][nt][3] + b1);
            } else {
                float* C = (float*)Cg;
                *(float2*)(C + (size_t)row * N + col) =
                    make_float2(acc[mt][nt][0] + b0, acc[mt][nt][1] + b1);
                *(float2*)(C + (size_t)(row + 8) * N + col) =
                    make_float2(acc[mt][nt][2] + b0, acc[mt][nt][3] + b1);
            }
        }
    }
}

// ---------------- tensor-core GRU recurrence ----------------------------------
// New mapping: each warp owns an 8-col n-slice (4 j's, r/u interleaved) with
// FULL k=256 (16 chained mma, 4 interleaved acc sets). Gate pre-activations come
// straight out of mma accumulators — no partial-sum smem round trip.
#define HS_PITCH 264                     // halfs per h-stage row (256 + 8 pad)
#define WST_PITCH 136
#define WST_BYTES (256 * WST_PITCH * 2)  // 69632
#define BAR_OFF  WST_BYTES
#define GRU_SMEM (WST_BYTES + 64)

__global__ __launch_bounds__(512, 1) __cluster_dims__(4, 1, 1)
void gru_rec_tc() {
    extern __shared__ char smc[];
    __half* wstage = (__half*)smc;
    __half* hstage = (__half*)smc;                 // [2][16][HS_PITCH]
    const uint32_t smb  = (uint32_t)__cvta_generic_to_shared(smc);
    const uint32_t barb = smb + BAR_OFF;

    const int tid  = threadIdx.x;
    const int wid  = tid >> 5;
    const int lane = tid & 31;
    uint32_t rank;
    asm("mov.u32 %0, %%cluster_ctarank;" : "=r"(rank));
    const int q = (int)rank;
    const int g = blockIdx.x >> 2;

    // ---- stage weight slice [256 k][128 n] (r/u interleaved) ----
    {
        const uint4* src = (const uint4*)g_wrec + (size_t)q * 4096;
#pragma unroll
        for (int it = 0; it < 8; it++) {
            int idx = it * 512 + tid;
            int row = idx >> 4;
            int cu  = idx & 15;
            *(uint4*)(wstage + row * WST_PITCH + cu * 8) = src[idx];
        }
    }
    __syncthreads();

    const int nsl = wid;         // n-slice: cols [nsl*8, nsl*8+8)
    uint32_t Breg[16][2];        // k16 x n8 fragments for all 16 k-steps
#pragma unroll
    for (int kk = 0; kk < 16; kk++)
        ldmatrix_x2t(Breg[kk],
                     wstage + (kk * 16 + (lane & 15)) * WST_PITCH + nsl * 8);
    __syncthreads();   // weight stage dead; smem reused for hstage

    if (tid == 0) { bar_init(barb, 1); bar_init(barb + 8, 1); }
    asm volatile("barrier.cluster.arrive.aligned;" ::: "memory");
    asm volatile("barrier.cluster.wait.aligned;" ::: "memory");

    // ---- per-thread identity: rows r0 & r0+8, single j ----
    const int r0  = lane >> 2;            // 0..7
    const int r8  = r0 + 8;
    const int jl  = nsl * 4 + (lane & 3); // local j 0..63
    const int jg  = q * 64 + jl;          // global j
    const int c0  = g * 16 + r0;
    const int c8  = g * 16 + r8;
    const int b0  = c0 >> 1;
    const int b8  = c8 >> 1;
    const int dir = c0 & 1;               // same parity for r8
    const size_t brow0 = (size_t)b0 * LSZ;
    const size_t brow8 = (size_t)b8 * LSZ;
    __half* __restrict__ hout = dir ? g_hb : g_hf;

    const bool evenj = ((lane & 1) == 0);
    const int  jpair = jg & ~1;

    float hv0 = 0.f, hv8 = 0.f;

    // prefetch xg for s=0 (both rows)
    float xx0c, xr0c, xu0c, xx8c, xr8c, xu8c;
    {
        int t0 = dir ? (LSZ - 1) : 0;
        const float* p0 = g_xg + (brow0 + t0) * (3 * DSZ) + jg;
        const float* p8 = g_xg + (brow8 + t0) * (3 * DSZ) + jg;
        xx0c = p0[0]; xr0c = p0[256]; xu0c = p0[512];
        xx8c = p8[0]; xr8c = p8[256]; xu8c = p8[512];
    }

    const int al_r = lane & 15;
    const int al_c = (lane >> 4) << 3;

    for (int s = 0; s < LSZ; s++) {
        const int bb = s & 1, nb = bb ^ 1;

        float xx0n, xr0n, xu0n, xx8n, xr8n, xu8n;
        if (s < LSZ - 1) {
            int tn = dir ? (LSZ - 2 - s) : (s + 1);
            const float* p0 = g_xg + (brow0 + tn) * (3 * DSZ) + jg;
            const float* p8 = g_xg + (brow8 + tn) * (3 * DSZ) + jg;
            xx0n = p0[0]; xr0n = p0[256]; xu0n = p0[512];
            xx8n = p8[0]; xr8n = p8[256]; xu8n = p8[512];
        }
        if (tid == 0 && s < LSZ - 1) bar_expect_tx(barb + nb * 8, 6144);

        float g0 = 0.f, g1 = 0.f, g2 = 0.f, g3 = 0.f;   // r0-r, r0-u, r8-r, r8-u
        if (s > 0) {
            int n = (s & 1) ? ((s - 1) >> 1) : ((s >> 1) - 1);
            bar_wait(barb + bb * 8, (uint32_t)(n & 1));

            float acc[4][4];
#pragma unroll
            for (int a4 = 0; a4 < 4; a4++)
#pragma unroll
                for (int i = 0; i < 4; i++) acc[a4][i] = 0.f;
            const __half* hcur = hstage + bb * 16 * HS_PITCH;
#pragma unroll
            for (int kk = 0; kk < 16; kk++) {
                uint32_t a[4];
                ldmatrix_x4(a, hcur + al_r * HS_PITCH + kk * 16 + al_c);
                mma16816(acc[kk & 3], a, Breg[kk]);
            }
            g0 = (acc[0][0] + acc[1][0]) + (acc[2][0] + acc[3][0]);
            g1 = (acc[0][1] + acc[1][1]) + (acc[2][1] + acc[3][1]);
            g2 = (acc[0][2] + acc[1][2]) + (acc[2][2] + acc[3][2]);
            g3 = (acc[0][3] + acc[1][3]) + (acc[2][3] + acc[3][3]);
        }

        // ---- gates (tanh.approx everywhere; fp32 h state) ----
        float r0g = fmaf(0.5f, tanh_ap(0.5f * (g0 + xr0c)), 0.5f);
        float u0g = fmaf(0.5f, tanh_ap(0.5f * (g1 + xu0c)), 0.5f);
        float r8g = fmaf(0.5f, tanh_ap(0.5f * (g2 + xr8c)), 0.5f);
        float u8g = fmaf(0.5f, tanh_ap(0.5f * (g3 + xu8c)), 0.5f);
        float xc0 = fmaf(r0g, hv0, xx0c);
        float xc8 = fmaf(r8g, hv8, xx8c);
        float th0 = tanh_ap(xc0);
        float th8 = tanh_ap(xc8);
        float hn0 = u0g * hv0 + (1.f - u0g) * th0;
        float hn8 = u8g * hv8 + (1.f - u8g) * th8;
        hv0 = hn0; hv8 = hn8;

        // ---- pair exchange: lane^1 swap -> (j, j+1) packed per row ----
        __half2 hhp = __floats2half2_rn(hn0, hn8);   // lo=row r0, hi=row r8
        uint32_t own = *(uint32_t*)&hhp;
        uint32_t oth = __shfl_xor_sync(0xffffffffu, own, 1);
        uint32_t outv = evenj ? ((own & 0xffffu) | (oth << 16))
                              : ((oth >> 16) | (own & 0xffff0000u));

        const int t = dir ? (LSZ - 1 - s) : s;
        // output: even-j lane writes row r0's (j,j+1); odd-j lane row r8's
        {
            size_t obase = evenj ? (brow0 + t) : (brow8 + t);
            *(uint32_t*)(hout + obase * DSZ + jpair) = outv;
        }

        if (s < LSZ - 1) {
            int srow = evenj ? r0 : r8;
            uint32_t loff = ((nb * 16 + srow) * HS_PITCH + jpair) * 2;
            // local slice: plain STS (ordered by trailing __syncthreads)
            *(uint32_t*)((char*)smc + loff) = outv;
            uint32_t laddr = smb + loff;
            uint32_t lbar  = barb + nb * 8;
#pragma unroll
            for (int rr = 0; rr < 4; rr++) {
                if (rr != q) {
                    uint32_t ra  = mapa_u32(laddr, (uint32_t)rr);
                    uint32_t rb2 = mapa_u32(lbar,  (uint32_t)rr);
                    st_async_b32(ra, outv, rb2);
                }
            }
        }
        __syncthreads();
        xx0c = xx0n; xr0c = xr0n; xu0c = xu0n;
        xx8c = xx8n; xr8c = xr8n; xu8c = xu8n;
    }

    asm volatile("barrier.cluster.arrive.aligned;" ::: "memory");
    asm volatile("barrier.cluster.wait.aligned;" ::: "memory");
}

// ---------------- launch ------------------------------------------------------
extern "C" void kernel_launch(void* const* d_in, const int* in_sizes, int n_in,
                              void* d_out, int out_size) {
    const float* inp  = (const float*)d_in[0];
    const float* Wi_w = (const float*)d_in[1];
    const float* Wi_b = (const float*)d_in[2];
    const float* Wx_w = (const float*)d_in[3];
    const float* Wx_b = (const float*)d_in[4];
    const float* Ux_w = (const float*)d_in[5];
    const float* Ux_b = (const float*)d_in[6];
    const float* Rx_w = (const float*)d_in[7];
    const float* Rx_b = (const float*)d_in[8];
    const float* Wr_w = (const float*)d_in[9];
    const float* Wr_b = (const float*)d_in[10];
    const float* Wu_w = (const float*)d_in[11];
    const float* Wu_b = (const float*)d_in[12];
    const float* Wo_w = (const float*)d_in[13];
    const float* Wo_b = (const float*)d_in[14];

    void *pxh, *pxg, *phf, *phb, *pwg, *pwo, *pbg;
    cudaGetSymbolAddress(&pxh, g_xh);
    cudaGetSymbolAddress(&pxg, g_xg);
    cudaGetSymbolAddress(&phf, g_hf);
    cudaGetSymbolAddress(&phb, g_hb);
    cudaGetSymbolAddress(&pwg, g_wg_h);
    cudaGetSymbolAddress(&pwo, g_wo_h);
    cudaGetSymbolAddress(&pbg, g_bg);

    cudaFuncSetAttribute(gemm_tc<1, 0>, cudaFuncAttributeMaxDynamicSharedMemorySize, SMEM_GEMM_BYTES);
    cudaFuncSetAttribute(gemm_tc<2, 0>, cudaFuncAttributeMaxDynamicSharedMemorySize, SMEM_GEMM_BYTES);
    cudaFuncSetAttribute(gru_rec_tc, cudaFuncAttributeMaxDynamicSharedMemorySize, GRU_SMEM);

    // pack recurrent weights + Wo ; convert inputs ; composite gate weights/bias
    prep_kernel<<<512, 256>>>(Wr_w, Wu_w, Wo_w);
    conv_inp<<<8192, 256>>>(inp);
    comp_w_kernel<<<dim3(12, 4), 256>>>(Wi_w, Wx_w, Ux_w, Rx_w);
    comp_b_kernel<<<768, 32>>>(Wi_b, Wx_w, Wx_b, Ux_w, Ux_b, Rx_w, Rx_b, Wr_b, Wu_b);

    // xg = xh @ W' + b'                  [65536,256] x [256,768] -> fp32
    gemm_tc<1, 0><<<dim3(6, 512), 256, SMEM_GEMM_BYTES>>>(
        pxh, nullptr, (const __half*)pwg, (const float*)pbg, pxg, 768);

    // bidirectional recurrence: 8 clusters of 4 CTAs, tensor-core steps
    gru_rec_tc<<<32, 512, GRU_SMEM>>>();

    // out = (hf + hb) @ Wo + bo          [65536,256] x [256,256] -> fp32
    gemm_tc<2, 0><<<dim3(2, 512), 256, SMEM_GEMM_BYTES>>>(
        phf, phb, (const __half*)pwo, Wo_b, d_out, 256);
}

// round 17
// speedup vs baseline: 2.4765x; 2.4765x over previous
#include <cuda_runtime.h>
#include <cuda_fp16.h>
#include <cstddef>
#include <cstdint>

#define BSZ 64
#define LSZ 1024
#define DSZ 256
#define NTOK (BSZ * LSZ)   // 65536 tokens

// ---------------- scratch (static __device__ — no allocations) ----------------
__device__ __half  g_xh[(size_t)NTOK * DSZ];        // 32 MB : inputs as fp16
__device__ float   g_xg[(size_t)NTOK * 3 * DSZ];    // 192 MB: [xx | xr' | xu'] per token (fp32)
__device__ __half  g_hf[(size_t)NTOK * DSZ];        // 32 MB : forward hidden states (fp16)
__device__ __half  g_hb[(size_t)NTOK * DSZ];        // 32 MB : backward hidden states (fp16)
__device__ __half  g_wo_h[DSZ * DSZ];               // Wo fp16
__device__ __half  g_wg_h[DSZ * 3 * DSZ];           // composite Wi@[Wx|Ux|Rx] fp16 (256 x 768)
__device__ float   g_bg[3 * DSZ];                   // composite biases
// recurrent weights for tc kernel: [q][k=256][n'=128] ; n'<64 -> Wr[:,q*64+n'], else Wu
__device__ __half  g_wrec[4 * 256 * 128];

// ---------------- prep: pack recurrent weights + Wo ---------------------------
__global__ void prep_kernel(const float* __restrict__ Wr, const float* __restrict__ Wu,
                            const float* __restrict__ Wo) {
    int i = blockIdx.x * blockDim.x + threadIdx.x;
    if (i < DSZ * DSZ) g_wo_h[i] = __float2half_rn(Wo[i]);
    if (i < 4 * 256 * 128) {
        int q = i >> 15;
        int k = (i >> 7) & 255;
        int n = i & 127;
        int col = q * 64 + (n < 64 ? n : n - 64);
        float v = (n < 64) ? Wr[k * DSZ + col] : Wu[k * DSZ + col];
        g_wrec[i] = __float2half_rn(v);
    }
}

// ---- convert inputs fp32 -> fp16 (once) --------------------------------------
__global__ __launch_bounds__(256) void conv_inp(const float* __restrict__ in) {
    size_t i = (size_t)blockIdx.x * blockDim.x + threadIdx.x;
    if (i >= (size_t)NTOK * DSZ / 8) return;
    float4 a = ((const float4*)in)[2 * i];
    float4 b = ((const float4*)in)[2 * i + 1];
    __half2 h[4] = { __floats2half2_rn(a.x, a.y), __floats2half2_rn(a.z, a.w),
                     __floats2half2_rn(b.x, b.y), __floats2half2_rn(b.z, b.w) };
    ((uint4*)g_xh)[i] = *(uint4*)h;
}

// ---- composite weight: W'[256][768] = Wi[256,256] @ [Wx|Ux|Rx], fp32 -> fp16
__global__ __launch_bounds__(256) void comp_w_kernel(
        const float* __restrict__ Wi, const float* __restrict__ Wx,
        const float* __restrict__ Ux, const float* __restrict__ Rx) {
    __shared__ float As[16][65];   // As[d][row]
    __shared__ float Bs[16][64];
    const int bn = blockIdx.x;     // 0..11
    const int bm = blockIdx.y;     // 0..3
    const float* src = (bn < 4) ? Wx : (bn < 8) ? Ux : Rx;
    const int nc0 = (bn & 3) * 64;
    const int tid = threadIdx.x;
    const int tx = tid & 15, ty = tid >> 4;

    float acc[4][4];
#pragma unroll
    for (int i = 0; i < 4; i++)
#pragma unroll
        for (int j = 0; j < 4; j++) acc[i][j] = 0.f;

    for (int d0 = 0; d0 < 256; d0 += 16) {
#pragma unroll
        for (int it = 0; it < 4; it++) {
            int idx = it * 256 + tid;
            int row = idx >> 4, c = idx & 15;
            As[c][row] = Wi[(bm * 64 + row) * 256 + d0 + c];
            int r2 = idx >> 6, c2 = idx & 63;
            Bs[r2][c2] = src[(d0 + r2) * 256 + nc0 + c2];
        }
        __syncthreads();
#pragma unroll
        for (int k = 0; k < 16; k++) {
            float a[4], b[4];
#pragma unroll
            for (int i = 0; i < 4; i++) a[i] = As[k][ty * 4 + i];
#pragma unroll
            for (int j = 0; j < 4; j++) b[j] = Bs[k][tx * 4 + j];
#pragma unroll
            for (int i = 0; i < 4; i++)
#pragma unroll
                for (int j = 0; j < 4; j++) acc[i][j] = fmaf(a[i], b[j], acc[i][j]);
        }
        __syncthreads();
    }
#pragma unroll
    for (int i = 0; i < 4; i++)
#pragma unroll
        for (int j = 0; j < 4; j++)
            g_wg_h[(size_t)(bm * 64 + ty * 4 + i) * 768 + bn * 64 + tx * 4 + j] =
                __float2half_rn(acc[i][j]);
}

// ---- composite bias: warp-parallel (768 blocks x 32 lanes) -------------------
__global__ void comp_b_kernel(const float* __restrict__ bi,
                              const float* __restrict__ Wx, const float* __restrict__ Wxb,
                              const float* __restrict__ Ux, const float* __restrict__ Uxb,
                              const float* __restrict__ Rx, const float* __restrict__ Rxb,
                              const float* __restrict__ Wrb, const float* __restrict__ Wub) {
    int n = blockIdx.x;
    int lane = threadIdx.x;
    const float* src; int nl; float base;
    if (n < 256)      { src = Wx; nl = n;       base = Wxb[nl]; }
    else if (n < 512) { src = Ux; nl = n - 256; base = Uxb[nl] + Wrb[nl]; }
    else              { src = Rx; nl = n - 512; base = Rxb[nl] + Wub[nl]; }
    float s = 0.f;
    for (int d = lane; d < 256; d += 32) s = fmaf(bi[d], src[d * 256 + nl], s);
#pragma unroll
    for (int off = 16; off; off >>= 1) s += __shfl_xor_sync(0xffffffffu, s, off);
    if (lane == 0) g_bg[n] = s + base;
}

// ---------------- mma / ldmatrix helpers --------------------------------------
__device__ __forceinline__ void ldmatrix_x4(uint32_t* r, const __half* p) {
    uint32_t addr = (uint32_t)__cvta_generic_to_shared(p);
    asm volatile("ldmatrix.sync.aligned.m8n8.x4.shared.b16 {%0,%1,%2,%3}, [%4];"
                 : "=r"(r[0]), "=r"(r[1]), "=r"(r[2]), "=r"(r[3]) : "r"(addr));
}
__device__ __forceinline__ void ldmatrix_x2t(uint32_t* r, const __half* p) {
    uint32_t addr = (uint32_t)__cvta_generic_to_shared(p);
    asm volatile("ldmatrix.sync.aligned.m8n8.x2.trans.shared.b16 {%0,%1}, [%2];"
                 : "=r"(r[0]), "=r"(r[1]) : "r"(addr));
}
__device__ __forceinline__ void mma16816(float* c, const uint32_t* a, const uint32_t* b) {
    asm volatile("mma.sync.aligned.m16n8k16.row.col.f32.f16.f16.f32 "
                 "{%0,%1,%2,%3}, {%4,%5,%6,%7}, {%8,%9}, {%0,%1,%2,%3};"
                 : "+f"(c[0]), "+f"(c[1]), "+f"(c[2]), "+f"(c[3])
                 : "r"(a[0]), "r"(a[1]), "r"(a[2]), "r"(a[3]), "r"(b[0]), "r"(b[1]));
}
__device__ __forceinline__ float tanh_ap(float x) {
    float y; asm("tanh.approx.f32 %0, %1;" : "=f"(y) : "f"(x)); return y;
}

// ---------------- mbarrier / cluster helpers ----------------------------------
__device__ __forceinline__ void bar_init(uint32_t bar, uint32_t cnt) {
    asm volatile("mbarrier.init.shared.b64 [%0], %1;" :: "r"(bar), "r"(cnt) : "memory");
}
__device__ __forceinline__ void bar_expect_tx(uint32_t bar, uint32_t bytes) {
    asm volatile("mbarrier.arrive.expect_tx.shared.b64 _, [%0], %1;"
                 :: "r"(bar), "r"(bytes) : "memory");
}
__device__ __forceinline__ void bar_wait(uint32_t bar, uint32_t phase) {
    asm volatile(
        "{\n\t.reg .pred P;\n\t"
        "WL_%=:\n\t"
        "mbarrier.try_wait.parity.acquire.cta.shared::cta.b64 P, [%0], %1, 0x989680;\n\t"
        "@P bra WD_%=;\n\t"
        "bra WL_%=;\n\t"
        "WD_%=:\n\t}"
        :: "r"(bar), "r"(phase) : "memory");
}
__device__ __forceinline__ uint32_t mapa_u32(uint32_t laddr, uint32_t rank) {
    uint32_t r;
    asm volatile("mapa.shared::cluster.u32 %0, %1, %2;" : "=r"(r) : "r"(laddr), "r"(rank));
    return r;
}
__device__ __forceinline__ void st_async_b32(uint32_t raddr, uint32_t val, uint32_t rbar) {
    asm volatile("st.async.shared::cluster.mbarrier::complete_tx::bytes.b32 [%0], %1, [%2];"
                 :: "r"(raddr), "r"(val), "r"(rbar) : "memory");
}

// ---------------- tensor-core GEMM (R14 — validated, unchanged) ----------------
#define A_LD 264
#define B2_LD 136
#define SMEM_GEMM_BYTES ((128 * A_LD + 128 * B2_LD) * 2)   // 102400

template<int AMODE, int OUTH>
__global__ __launch_bounds__(256, 2) void gemm_tc(
        const void* __restrict__ Aa, const void* __restrict__ Ab,
        const __half* __restrict__ Bg, const float* __restrict__ bias,
        void* __restrict__ Cg, int N) {
    extern __shared__ __half sm[];
    __half* As = sm;                     // [128][A_LD]
    __half* Bs = sm + 128 * A_LD;        // [128][B2_LD]

    const int tid  = threadIdx.x;
    const int bm   = blockIdx.y * 128;
    const int bn   = blockIdx.x * 128;
    const int nq   = N >> 3;

    const int wid  = tid >> 5;
    const int lane = tid & 31;
    const int wm   = (wid & 3) * 32;
    const int wn   = (wid >> 2) * 64;
    const int al_r = lane & 15;
    const int al_c = (lane >> 4) << 3;

#pragma unroll
    for (int it = 0; it < 16; it++) {
        int idx = it * 256 + tid;
        int row = idx >> 5;
        int cu  = idx & 31;
        uint4 v;
        if (AMODE == 1) {
            v = ((const uint4*)Aa)[(size_t)(bm + row) * 32 + cu];
        } else {
            uint4 p = ((const uint4*)Aa)[(size_t)(bm + row) * 32 + cu];
            uint4 q = ((const uint4*)Ab)[(size_t)(bm + row) * 32 + cu];
            __half2* pp = (__half2*)&p; const __half2* qq = (const __half2*)&q;
            pp[0] = __hadd2(pp[0], qq[0]); pp[1] = __hadd2(pp[1], qq[1]);
            pp[2] = __hadd2(pp[2], qq[2]); pp[3] = __hadd2(pp[3], qq[3]);
            v = p;
        }
        *(uint4*)(As + row * A_LD + cu * 8) = v;
    }

    float acc[2][8][4];
#pragma unroll
    for (int mt = 0; mt < 2; mt++)
#pragma unroll
        for (int nt = 0; nt < 8; nt++)
#pragma unroll
            for (int i = 0; i < 4; i++) acc[mt][nt][i] = 0.f;

#pragma unroll
    for (int ks2 = 0; ks2 < 2; ks2++) {
        if (ks2) __syncthreads();

#pragma unroll
        for (int it = 0; it < 8; it++) {
            int idx = it * 256 + tid;
            int row = idx >> 4;
            int cu  = idx & 15;
            uint4 v = ((const uint4*)Bg)[(size_t)(ks2 * 128 + row) * nq + (bn >> 3) + cu];
            *(uint4*)(Bs + row * B2_LD + cu * 8) = v;
        }
        __syncthreads();

#pragma unroll
        for (int ks = 0; ks < 8; ks++) {
            const int k0a = ks2 * 128 + ks * 16;
            const int k0b = ks * 16;
            uint32_t a[2][4], b[8][2];
#pragma unroll
            for (int mt = 0; mt < 2; mt++)
                ldmatrix_x4(a[mt], As + (wm + mt * 16 + al_r) * A_LD + k0a + al_c);
#pragma unroll
            for (int nt = 0; nt < 8; nt++)
                ldmatrix_x2t(b[nt], Bs + (k0b + al_r) * B2_LD + wn + nt * 8);
#pragma unroll
            for (int mt = 0; mt < 2; mt++)
#pragma unroll
                for (int nt = 0; nt < 8; nt++)
                    mma16816(acc[mt][nt], a[mt], b[nt]);
        }
    }

#pragma unroll
    for (int mt = 0; mt < 2; mt++) {
#pragma unroll
        for (int nt = 0; nt < 8; nt++) {
            int row = bm + wm + mt * 16 + (lane >> 2);
            int col = bn + wn + nt * 8 + (lane & 3) * 2;
            float b0 = bias[col], b1 = bias[col + 1];
            if (OUTH) {
                __half* C = (__half*)Cg;
                *(__half2*)(C + (size_t)row * N + col) =
                    __floats2half2_rn(acc[mt][nt][0] + b0, acc[mt][nt][1] + b1);
                *(__half2*)(C + (size_t)(row + 8) * N + col) =
                    __floats2half2_rn(acc[mt][nt][2] + b0, acc[mt][nt][3] + b1);
            } else {
                float* C = (float*)Cg;
                *(float2*)(C + (size_t)row * N + col) =
                    make_float2(acc[mt][nt][0] + b0, acc[mt][nt][1] + b1);
                *(float2*)(C + (size_t)(row + 8) * N + col) =
                    make_float2(acc[mt][nt][2] + b0, acc[mt][nt][3] + b1);
            }
        }
    }
}

// ---------------- tensor-core GRU recurrence (R14 structure, proven) ----------
// Per warp: one sequence row, k-split over 4 warp-groups, smem partial reduce.
// Self-slice via STS; remote via st.async; all nonlinearities tanh.approx.
#define HS_PITCH 264                     // halfs per h-stage row
#define P_PITCH  132                     // floats per partial row
#define HS_BYTES (2 * 16 * HS_PITCH * 2) // 16896
#define P_OFF    HS_BYTES
#define WST_PITCH 136
#define WST_BYTES (256 * WST_PITCH * 2)  // 69632
#define BAR_OFF  WST_BYTES
#define GRU_SMEM (WST_BYTES + 64)

__global__ __launch_bounds__(512, 1) __cluster_dims__(4, 1, 1)
void gru_rec_tc() {
    extern __shared__ char smc[];
    __half* wstage = (__half*)smc;
    __half* hstage = (__half*)smc;                 // [2][16][HS_PITCH]
    float*  Pbuf   = (float*)(smc + P_OFF);        // [4][16][P_PITCH]
    const uint32_t smb   = (uint32_t)__cvta_generic_to_shared(smc);
    const uint32_t barb  = smb + BAR_OFF;

    const int tid  = threadIdx.x;
    const int wid  = tid >> 5;
    const int lane = tid & 31;
    uint32_t rank;
    asm("mov.u32 %0, %%cluster_ctarank;" : "=r"(rank));
    const int q = (int)rank;
    const int g = blockIdx.x >> 2;

    {
        const uint4* src = (const uint4*)g_wrec + (size_t)q * 4096;
#pragma unroll
        for (int it = 0; it < 8; it++) {
            int idx = it * 512 + tid;
            int row = idx >> 4;
            int cu  = idx & 15;
            *(uint4*)(wstage + row * WST_PITCH + cu * 8) = src[idx];
        }
    }
    __syncthreads();

    const int kq  = wid & 3;     // k-quarter
    const int nql = wid >> 2;    // n-quarter
    uint32_t Breg[4][4][2];
#pragma unroll
    for (int kk = 0; kk < 4; kk++)
#pragma unroll
        for (int nt = 0; nt < 4; nt++)
            ldmatrix_x2t(Breg[kk][nt],
                         wstage + (kq * 64 + kk * 16 + (lane & 15)) * WST_PITCH
                                + nql * 32 + nt * 8);
    __syncthreads();   // weight stage dead; smem reused

    if (tid == 0) { bar_init(barb, 1); bar_init(barb + 8, 1); }
    asm volatile("barrier.cluster.arrive.aligned;" ::: "memory");
    asm volatile("barrier.cluster.wait.aligned;" ::: "memory");

    const int row = wid;
    const int jl  = lane * 2;
    const int jg  = q * 64 + jl;
    const int c   = g * 16 + row;
    const int b   = c >> 1;
    const int dir = c & 1;
    const size_t browb = (size_t)b * LSZ;
    __half* __restrict__ hout = dir ? g_hb : g_hf;

    float hvx = 0.f, hvy = 0.f;

    float2 xx_c, xr_c, xu_c;
    {
        int t0 = dir ? (LSZ - 1) : 0;
        const float* xgp = g_xg + (browb + t0) * (3 * DSZ);
        xx_c = *(const float2*)(xgp + jg);
        xr_c = *(const float2*)(xgp + 256 + jg);
        xu_c = *(const float2*)(xgp + 512 + jg);
    }

    const uint32_t hs_l0 = smb;
    const int al_r = lane & 15;
    const int al_c = (lane >> 4) << 3;

    for (int s = 0; s < LSZ; s++) {
        const int bb = s & 1, nb = bb ^ 1;

        float2 xx_n, xr_n, xu_n;
        if (s < LSZ - 1) {
            int tn = dir ? (LSZ - 2 - s) : (s + 1);
            const float* xgp = g_xg + (browb + tn) * (3 * DSZ);
            xx_n = *(const float2*)(xgp + jg);
            xr_n = *(const float2*)(xgp + 256 + jg);
            xu_n = *(const float2*)(xgp + 512 + jg);
        }
        // remote-only tx: 3 ranks x 512 threads x 4B = 6144 bytes
        if (tid == 0 && s < LSZ - 1) bar_expect_tx(barb + nb * 8, 6144);

        float rpx = 0.f, rpy = 0.f, upx = 0.f, upy = 0.f;
        if (s > 0) {
            int n = (s & 1) ? ((s - 1) >> 1) : ((s >> 1) - 1);
            bar_wait(barb + bb * 8, (uint32_t)(n & 1));

            float acc[4][4];
#pragma unroll
            for (int nt = 0; nt < 4; nt++)
#pragma unroll
                for (int i = 0; i < 4; i++) acc[nt][i] = 0.f;
            const __half* hcur = hstage + bb * 16 * HS_PITCH;
#pragma unroll
            for (int kk = 0; kk < 4; kk++) {
                uint32_t a[4];
                ldmatrix_x4(a, hcur + al_r * HS_PITCH + kq * 64 + kk * 16 + al_c);
#pragma unroll
                for (int nt = 0; nt < 4; nt++)
                    mma16816(acc[nt], a, Breg[kk][nt]);
            }
            {
                int r0 = lane >> 2, cp = (lane & 3) * 2;
#pragma unroll
                for (int nt = 0; nt < 4; nt++) {
                    int col = nql * 32 + nt * 8 + cp;
                    float* p = Pbuf + (kq * 16 + r0) * P_PITCH + col;
                    *(float2*)p = make_float2(acc[nt][0], acc[nt][1]);
                    *(float2*)(p + 8 * P_PITCH) = make_float2(acc[nt][2], acc[nt][3]);
                }
            }
            __syncthreads();
#pragma unroll
            for (int k2 = 0; k2 < 4; k2++) {
                const float* pp = Pbuf + (k2 * 16 + row) * P_PITCH;
                float2 a = *(const float2*)(pp + jl);
                float2 bq = *(const float2*)(pp + 64 + jl);
                rpx += a.x; rpy += a.y; upx += bq.x; upy += bq.y;
            }
        }

        // ---- gates: all nonlinearities via tanh.approx ----
        float grx = rpx + xr_c.x, gry = rpy + xr_c.y;
        float gux = upx + xu_c.x, guy = upy + xu_c.y;
        float r0 = fmaf(0.5f, tanh_ap(0.5f * grx), 0.5f);
        float r1 = fmaf(0.5f, tanh_ap(0.5f * gry), 0.5f);
        float u0 = fmaf(0.5f, tanh_ap(0.5f * gux), 0.5f);
        float u1 = fmaf(0.5f, tanh_ap(0.5f * guy), 0.5f);
        float xc0 = fmaf(r0, hvx, xx_c.x);
        float xc1 = fmaf(r1, hvy, xx_c.y);
        float th0 = tanh_ap(xc0);
        float th1 = tanh_ap(xc1);
        float hn0 = u0 * hvx + (1.f - u0) * th0;
        float hn1 = u1 * hvy + (1.f - u1) * th1;
        hvx = hn0; hvy = hn1;

        __half2 hh = __floats2half2_rn(hn0, hn1);
        uint32_t val = *(uint32_t*)&hh;

        if (s < LSZ - 1) {
            // DSMEM sends FIRST — they gate the peers' next bar_wait.
            uint32_t loff  = ((nb * 16 + row) * HS_PITCH + jg) * 2;
            uint32_t laddr = hs_l0 + loff;
            uint32_t lbar  = barb + nb * 8;
#pragma unroll
            for (int rr = 0; rr < 4; rr++) {
                if (rr != q) {
                    uint32_t ra  = mapa_u32(laddr, (uint32_t)rr);
                    uint32_t rb2 = mapa_u32(lbar,  (uint32_t)rr);
                    st_async_b32(ra, val, rb2);
                }
            }
            // local slice via plain STS (ordered by trailing __syncthreads)
            *(uint32_t*)((char*)smc + loff) = val;
        }

        // fire-and-forget global output store (off critical path)
        const int t = dir ? (LSZ - 1 - s) : s;
        *(uint32_t*)(hout + (browb + t) * DSZ + jg) = val;

        __syncthreads();
        xx_c = xx_n; xr_c = xr_n; xu_c = xu_n;
    }

    asm volatile("barrier.cluster.arrive.aligned;" ::: "memory");
    asm volatile("barrier.cluster.wait.aligned;" ::: "memory");
}

// ---------------- launch ------------------------------------------------------
extern "C" void kernel_launch(void* const* d_in, const int* in_sizes, int n_in,
                              void* d_out, int out_size) {
    const float* inp  = (const float*)d_in[0];
    const float* Wi_w = (const float*)d_in[1];
    const float* Wi_b = (const float*)d_in[2];
    const float* Wx_w = (const float*)d_in[3];
    const float* Wx_b = (const float*)d_in[4];
    const float* Ux_w = (const float*)d_in[5];
    const float* Ux_b = (const float*)d_in[6];
    const float* Rx_w = (const float*)d_in[7];
    const float* Rx_b = (const float*)d_in[8];
    const float* Wr_w = (const float*)d_in[9];
    const float* Wr_b = (const float*)d_in[10];
    const float* Wu_w = (const float*)d_in[11];
    const float* Wu_b = (const float*)d_in[12];
    const float* Wo_w = (const float*)d_in[13];
    const float* Wo_b = (const float*)d_in[14];

    void *pxh, *pxg, *phf, *phb, *pwg, *pwo, *pbg;
    cudaGetSymbolAddress(&pxh, g_xh);
    cudaGetSymbolAddress(&pxg, g_xg);
    cudaGetSymbolAddress(&phf, g_hf);
    cudaGetSymbolAddress(&phb, g_hb);
    cudaGetSymbolAddress(&pwg, g_wg_h);
    cudaGetSymbolAddress(&pwo, g_wo_h);
    cudaGetSymbolAddress(&pbg, g_bg);

    cudaFuncSetAttribute(gemm_tc<1, 0>, cudaFuncAttributeMaxDynamicSharedMemorySize, SMEM_GEMM_BYTES);
    cudaFuncSetAttribute(gemm_tc<2, 0>, cudaFuncAttributeMaxDynamicSharedMemorySize, SMEM_GEMM_BYTES);
    cudaFuncSetAttribute(gru_rec_tc, cudaFuncAttributeMaxDynamicSharedMemorySize, GRU_SMEM);

    // pack recurrent weights + Wo ; convert inputs ; composite gate weights/bias
    prep_kernel<<<512, 256>>>(Wr_w, Wu_w, Wo_w);
    conv_inp<<<8192, 256>>>(inp);
    comp_w_kernel<<<dim3(12, 4), 256>>>(Wi_w, Wx_w, Ux_w, Rx_w);
    comp_b_kernel<<<768, 32>>>(Wi_b, Wx_w, Wx_b, Ux_w, Ux_b, Rx_w, Rx_b, Wr_b, Wu_b);

    // xg = xh @ W' + b'                  [65536,256] x [256,768] -> fp32
    gemm_tc<1, 0><<<dim3(6, 512), 256, SMEM_GEMM_BYTES>>>(
        pxh, nullptr, (const __half*)pwg, (const float*)pbg, pxg, 768);

    // bidirectional recurrence: 8 clusters of 4 CTAs, tensor-core steps
    gru_rec_tc<<<32, 512, GRU_SMEM>>>();

    // out = (hf + hb) @ Wo + bo          [65536,256] x [256,256] -> fp32
    gemm_tc<2, 0><<<dim3(2, 512), 256, SMEM_GEMM_BYTES>>>(
        phf, phb, (const __half*)pwo, Wo_b, d_out, 256);
}